// round 6
// baseline (speedup 1.0000x reference)
#include <cuda_runtime.h>

#define Bn 4
#define Tn 4096
#define En 1024
#define Hn 64
#define SCALE 0.03125f   // 1024^-0.5

typedef unsigned uu;

// Projected q/k/v scratch: [B,T,H] fp32
__device__ float g_q[Bn * Tn * Hn];
__device__ float g_k[Bn * Tn * Hn];
__device__ float g_v[Bn * Tn * Hn];

__device__ __forceinline__ uu f2tf(float f) {
    uu r; asm("cvt.rna.tf32.f32 %0, %1;" : "=r"(r) : "f"(f)); return r;
}

// D += A(16x8,row) * B(8x8,col), tf32 in, fp32 accum
__device__ __forceinline__ void mma8(float c[4], const uu a[4], const uu b[2]) {
    asm("mma.sync.aligned.m16n8k8.row.col.f32.tf32.tf32.f32 "
        "{%0,%1,%2,%3}, {%4,%5,%6,%7}, {%8,%9}, {%0,%1,%2,%3};"
        : "+f"(c[0]), "+f"(c[1]), "+f"(c[2]), "+f"(c[3])
        : "r"(a[0]), "r"(a[1]), "r"(a[2]), "r"(a[3]), "r"(b[0]), "r"(b[1]));
}

// group-scoped named barrier (128 threads)
__device__ __forceinline__ void barg(int id) {
    asm volatile("bar.sync %0, %1;" :: "r"(id), "r"(128) : "memory");
}

__device__ __forceinline__ void cpa16(void* s, const void* g) {
    unsigned sa = (unsigned)__cvta_generic_to_shared(s);
    asm volatile("cp.async.ca.shared.global [%0], [%1], 16;" :: "r"(sa), "l"(g));
}
__device__ __forceinline__ void cpa_commit() {
    asm volatile("cp.async.commit_group;" ::: "memory");
}
__device__ __forceinline__ void cpa_wait1() {
    asm volatile("cp.async.wait_group 1;" ::: "memory");
}
__device__ __forceinline__ void cpa_wait0() {
    asm volatile("cp.async.wait_group 0;" ::: "memory");
}

// ================= QKV projection (unchanged from R5) =================
#define PKC 32
#define XS_ST 36
#define WS_ST 196

__global__ void __launch_bounds__(128, 2) qkv_kernel(
    const float* __restrict__ x,  const float* __restrict__ Wq,
    const float* __restrict__ Wk, const float* __restrict__ Wv)
{
    extern __shared__ float smf[];
    float* xsb = smf;
    float* wsb = smf + 2 * 64 * XS_ST;

    const int tid = threadIdx.x;
    const int w = tid >> 5, lane = tid & 31, gr = lane >> 2, t = lane & 3;
    const int row0 = blockIdx.x * 64;
    const float* Ws[3] = { Wq, Wk, Wv };

    float acc[4][6][4];
#pragma unroll
    for (int rb = 0; rb < 4; rb++)
#pragma unroll
        for (int nt = 0; nt < 6; nt++)
#pragma unroll
            for (int c = 0; c < 4; c++) acc[rb][nt][c] = 0.f;

    auto issue = [&](int k0, int s) {
        float* xs = xsb + s * 64 * XS_ST;
        float* ws = wsb + s * PKC * WS_ST;
#pragma unroll
        for (int it = 0; it < 4; it++) {
            int idx = tid + it * 128;
            int r = idx >> 3, c = (idx & 7) * 4;
            cpa16(&xs[r * XS_ST + c], &x[(size_t)(row0 + r) * En + k0 + c]);
        }
#pragma unroll
        for (int it = 0; it < 12; it++) {
            int idx = tid + it * 128;
            int kk = idx / 48, n4 = (idx % 48) * 4;
            int m = n4 >> 6, col = n4 & 63;
            cpa16(&ws[kk * WS_ST + n4], &Ws[m][(size_t)(k0 + kk) * Hn + col]);
        }
    };

    issue(0, 0);
    cpa_commit();

    for (int it = 0; it < En / PKC; it++) {
        __syncthreads();
        if (it + 1 < En / PKC) issue((it + 1) * PKC, (it + 1) & 1);
        cpa_commit();
        cpa_wait1();
        __syncthreads();

        const float* xs = xsb + (it & 1) * 64 * XS_ST;
        const float* ws = wsb + (it & 1) * PKC * WS_ST;
#pragma unroll
        for (int kk = 0; kk < PKC / 8; kk++) {
            uu a[4][4];
#pragma unroll
            for (int rb = 0; rb < 4; rb++) {
                int r = rb * 16 + gr;
                a[rb][0] = f2tf(xs[r * XS_ST + kk * 8 + t]);
                a[rb][1] = f2tf(xs[(r + 8) * XS_ST + kk * 8 + t]);
                a[rb][2] = f2tf(xs[r * XS_ST + kk * 8 + t + 4]);
                a[rb][3] = f2tf(xs[(r + 8) * XS_ST + kk * 8 + t + 4]);
            }
#pragma unroll
            for (int nt = 0; nt < 6; nt++) {
                int n0 = w * 48 + nt * 8;
                uu b[2];
                b[0] = f2tf(ws[(kk * 8 + t) * WS_ST + n0 + gr]);
                b[1] = f2tf(ws[(kk * 8 + t + 4) * WS_ST + n0 + gr]);
#pragma unroll
                for (int rb = 0; rb < 4; rb++) mma8(acc[rb][nt], a[rb], b);
            }
        }
    }

#pragma unroll
    for (int nt = 0; nt < 6; nt++) {
        int n = w * 48 + nt * 8 + 2 * t;
        float* base = (n < 64) ? g_q : (n < 128 ? g_k : g_v);
        int nc = n & 63;
#pragma unroll
        for (int rb = 0; rb < 4; rb++) {
            int r = row0 + rb * 16 + gr;
            *(float2*)&base[(size_t)r * Hn + nc] =
                make_float2(acc[rb][nt][0], acc[rb][nt][1]);
            *(float2*)&base[(size_t)(r + 8) * Hn + nc] =
                make_float2(acc[rb][nt][2], acc[rb][nt][3]);
        }
    }
}

// ================= Flash attention: 3 kt-groups x (2x2) 32x32 warp tiles =================
// cp.async double-buffered K/V per group (raw fp32; tf32 cvt at fragment load).
// Per-warp independent online softmax over its 32-col strip; 6 partials merged.
#define AS 68
#define NG 3

__global__ void __launch_bounds__(384, 1) attn_kernel(float* __restrict__ out)
{
    extern __shared__ uu sm[];
    const int tid = threadIdx.x;
    const int w = tid >> 5, lane = tid & 31, gr = lane >> 2, t = lane & 3;
    const int g = w >> 2, wq = w & 3;
    const int rw = wq >> 1, cw = wq & 1;
    const int tg = tid & 127;

    uu* qs = sm;   // Q tile (tf32, scale folded): strip 0
    // staging strips 1..12: group g owns [1+4g .. 1+4g+3] = K0,V0,K1,V1 (raw fp32)
    float* K0 = (float*)(sm + (size_t)(1 + 4 * g) * 64 * AS);
    float* V0 = K0 + 64 * AS;
    float* K1 = V0 + 64 * AS;
    float* V1 = K1 + 64 * AS;
    float* Mg = (float*)(sm + (size_t)(1 + 2 * g + cw) * 64 * AS);  // merge (aliases staging)

    const int b = blockIdx.x & 3, pr = blockIdx.x >> 2;
    const float* kg = g_k + (size_t)b * Tn * Hn;
    const float* vg = g_v + (size_t)b * Tn * Hn;

    const int rbase = rw * 32, cbase = cw * 32;
    const int srcA = (lane & ~3) | (t >> 1);
    const int srcB = srcA + 2;

    for (int hf = 0; hf < 2; hf++) {
        const int qt = hf ? pr : 63 - pr;
        __syncthreads();   // previous half's combine readers done

        // Q tile -> smem (tf32, SCALE folded), all 384 threads
        const float* qg = g_q + ((size_t)b * Tn + qt * 64) * Hn;
        for (int idx = tid; idx < 1024; idx += 384) {
            int r = idx >> 4, c = (idx & 15) * 4;
            float4 v = *(const float4*)&qg[(size_t)r * Hn + c];
            *(uint4*)&qs[r * AS + c] = make_uint4(
                f2tf(v.x * SCALE), f2tf(v.y * SCALE),
                f2tf(v.z * SCALE), f2tf(v.w * SCALE));
        }
        __syncthreads();

        float o[2][8][4];
        float mm[2][2], ll[2][2];
#pragma unroll
        for (int rb = 0; rb < 2; rb++) {
            mm[rb][0] = mm[rb][1] = -1e30f;
            ll[rb][0] = ll[rb][1] = 0.f;
#pragma unroll
            for (int ht = 0; ht < 8; ht++)
#pragma unroll
                for (int c = 0; c < 4; c++) o[rb][ht][c] = 0.f;
        }

        // issue K/V tile kt into stage st
        auto issueKV = [&](int kt, int st) {
            const float* kp = kg + (size_t)kt * 64 * Hn;
            const float* vp = vg + (size_t)kt * 64 * Hn;
            float* kd = st ? K1 : K0;
            float* vd = st ? V1 : V0;
#pragma unroll
            for (int it = 0; it < 8; it++) {
                int idx = tg + it * 128;
                int r = idx >> 4, c = (idx & 15) * 4;
                cpa16(&kd[r * AS + c], &kp[(size_t)r * Hn + c]);
                cpa16(&vd[r * AS + c], &vp[(size_t)r * Hn + c]);
            }
        };

        if (g <= qt) { issueKV(g, 0); cpa_commit(); }

        int stage = 0;
        for (int kt = g; kt <= qt; kt += NG) {
            if (kt + NG <= qt) {
                barg(g + 1);                    // group done computing stage^1's old tile
                issueKV(kt + NG, stage ^ 1);
                cpa_commit();
                cpa_wait1();                    // current tile resident
            } else {
                cpa_wait0();
            }
            barg(g + 1);                        // visibility to whole group

            const float* ksf = stage ? K1 : K0;
            const float* vsf = stage ? V1 : V0;
            stage ^= 1;

            // ---- stage 1: S(32x32) = Q K^T ----
            float s[2][4][4];
#pragma unroll
            for (int rb = 0; rb < 2; rb++)
#pragma unroll
                for (int nt = 0; nt < 4; nt++)
#pragma unroll
                    for (int c = 0; c < 4; c++) s[rb][nt][c] = 0.f;
#pragma unroll
            for (int kk = 0; kk < 8; kk++) {
                uu qa[2][4];
#pragma unroll
                for (int rb = 0; rb < 2; rb++) {
                    int ra = (rbase + rb * 16 + gr) * AS;
                    qa[rb][0] = qs[ra + kk * 8 + t];
                    qa[rb][1] = qs[ra + 8 * AS + kk * 8 + t];
                    qa[rb][2] = qs[ra + kk * 8 + t + 4];
                    qa[rb][3] = qs[ra + 8 * AS + kk * 8 + t + 4];
                }
#pragma unroll
                for (int nt = 0; nt < 4; nt++) {
                    uu bf[2];
                    int kr = (cbase + nt * 8 + gr) * AS;
                    bf[0] = f2tf(ksf[kr + kk * 8 + t]);
                    bf[1] = f2tf(ksf[kr + kk * 8 + t + 4]);
                    mma8(s[0][nt], qa[0], bf);
                    mma8(s[1][nt], qa[1], bf);
                }
            }

            if (kt == qt) {   // causal mask on diagonal tile
#pragma unroll
                for (int rb = 0; rb < 2; rb++) {
                    int r0 = rbase + rb * 16 + gr, r1 = r0 + 8;
#pragma unroll
                    for (int nt = 0; nt < 4; nt++) {
                        int c0 = cbase + nt * 8 + 2 * t;
                        if (c0 > r0)     s[rb][nt][0] = -1e30f;
                        if (c0 + 1 > r0) s[rb][nt][1] = -1e30f;
                        if (c0 > r1)     s[rb][nt][2] = -1e30f;
                        if (c0 + 1 > r1) s[rb][nt][3] = -1e30f;
                    }
                }
            }

            // ---- online softmax (per rb; this warp's 32-col strip) ----
#pragma unroll
            for (int rb = 0; rb < 2; rb++) {
                float rm0 = -1e30f, rm1 = -1e30f;
#pragma unroll
                for (int nt = 0; nt < 4; nt++) {
                    rm0 = fmaxf(rm0, fmaxf(s[rb][nt][0], s[rb][nt][1]));
                    rm1 = fmaxf(rm1, fmaxf(s[rb][nt][2], s[rb][nt][3]));
                }
                rm0 = fmaxf(rm0, __shfl_xor_sync(~0u, rm0, 1));
                rm0 = fmaxf(rm0, __shfl_xor_sync(~0u, rm0, 2));
                rm1 = fmaxf(rm1, __shfl_xor_sync(~0u, rm1, 1));
                rm1 = fmaxf(rm1, __shfl_xor_sync(~0u, rm1, 2));
                float nm0 = fmaxf(mm[rb][0], rm0), nm1 = fmaxf(mm[rb][1], rm1);
                float cr0 = __expf(mm[rb][0] - nm0), cr1 = __expf(mm[rb][1] - nm1);
                mm[rb][0] = nm0; mm[rb][1] = nm1;

                float rs0 = 0.f, rs1 = 0.f;
#pragma unroll
                for (int nt = 0; nt < 4; nt++) {
                    float p0 = __expf(s[rb][nt][0] - nm0), p1 = __expf(s[rb][nt][1] - nm0);
                    float p2 = __expf(s[rb][nt][2] - nm1), p3 = __expf(s[rb][nt][3] - nm1);
                    rs0 += p0 + p1; rs1 += p2 + p3;
                    s[rb][nt][0] = __uint_as_float(f2tf(p0));
                    s[rb][nt][1] = __uint_as_float(f2tf(p1));
                    s[rb][nt][2] = __uint_as_float(f2tf(p2));
                    s[rb][nt][3] = __uint_as_float(f2tf(p3));
                }
                rs0 += __shfl_xor_sync(~0u, rs0, 1);
                rs0 += __shfl_xor_sync(~0u, rs0, 2);
                rs1 += __shfl_xor_sync(~0u, rs1, 1);
                rs1 += __shfl_xor_sync(~0u, rs1, 2);
                ll[rb][0] = ll[rb][0] * cr0 + rs0;
                ll[rb][1] = ll[rb][1] * cr1 + rs1;
#pragma unroll
                for (int ht = 0; ht < 8; ht++) {
                    o[rb][ht][0] *= cr0; o[rb][ht][1] *= cr0;
                    o[rb][ht][2] *= cr1; o[rb][ht][3] *= cr1;
                }
            }

            // ---- stage 2: O += P V (P A-frags via shuffle) ----
#pragma unroll
            for (int kk = 0; kk < 4; kk++) {
                uu pa[2][4];
#pragma unroll
                for (int rb = 0; rb < 2; rb++) {
                    float u0 = __shfl_sync(~0u, s[rb][kk][0], srcA);
                    float u1 = __shfl_sync(~0u, s[rb][kk][1], srcA);
                    float u2 = __shfl_sync(~0u, s[rb][kk][2], srcA);
                    float u3 = __shfl_sync(~0u, s[rb][kk][3], srcA);
                    float v0 = __shfl_sync(~0u, s[rb][kk][0], srcB);
                    float v1 = __shfl_sync(~0u, s[rb][kk][1], srcB);
                    float v2 = __shfl_sync(~0u, s[rb][kk][2], srcB);
                    float v3 = __shfl_sync(~0u, s[rb][kk][3], srcB);
                    pa[rb][0] = __float_as_uint((t & 1) ? u1 : u0);
                    pa[rb][1] = __float_as_uint((t & 1) ? u3 : u2);
                    pa[rb][2] = __float_as_uint((t & 1) ? v1 : v0);
                    pa[rb][3] = __float_as_uint((t & 1) ? v3 : v2);
                }
#pragma unroll
                for (int ht = 0; ht < 8; ht++) {
                    uu vb[2];
                    vb[0] = f2tf(vsf[(cbase + kk * 8 + t) * AS + ht * 8 + gr]);
                    vb[1] = f2tf(vsf[(cbase + kk * 8 + t + 4) * AS + ht * 8 + gr]);
                    mma8(o[0][ht], pa[0], vb);
                    mma8(o[1][ht], pa[1], vb);
                }
            }
        }

        // ---- dump 6 partials into strips 1..6 (staging dead now) ----
        __syncthreads();
#pragma unroll
        for (int rb = 0; rb < 2; rb++) {
            int r0 = rbase + rb * 16 + gr, r1 = r0 + 8;
#pragma unroll
            for (int ht = 0; ht < 8; ht++) {
                *(float2*)&Mg[r0 * AS + ht * 8 + 2 * t] = make_float2(o[rb][ht][0], o[rb][ht][1]);
                *(float2*)&Mg[r1 * AS + ht * 8 + 2 * t] = make_float2(o[rb][ht][2], o[rb][ht][3]);
            }
            if (t == 0) {
                Mg[r0 * AS + 64] = mm[rb][0]; Mg[r0 * AS + 65] = ll[rb][0];
                Mg[r1 * AS + 64] = mm[rb][1]; Mg[r1 * AS + 65] = ll[rb][1];
            }
        }
        __syncthreads();

        // ---- combine 6 partials, write output ----
        float* ob = out + ((size_t)b * Tn + qt * 64) * Hn;
        for (int idx = tid; idx < 1024; idx += 384) {
            int r = idx >> 4, c4 = (idx & 15) * 4;
            float mi[6], li[6], Mx = -1e30f;
#pragma unroll
            for (int i = 0; i < 6; i++) {
                const float* Mi = (const float*)(sm + (size_t)(1 + i) * 64 * AS);
                mi[i] = Mi[r * AS + 64];
                li[i] = Mi[r * AS + 65];
                Mx = fmaxf(Mx, mi[i]);
            }
            float L = 0.f, fi[6];
#pragma unroll
            for (int i = 0; i < 6; i++) {
                fi[i] = __expf(mi[i] - Mx);
                L += li[i] * fi[i];
            }
            float4 acc = make_float4(0.f, 0.f, 0.f, 0.f);
#pragma unroll
            for (int i = 0; i < 6; i++) {
                const float* Mi = (const float*)(sm + (size_t)(1 + i) * 64 * AS);
                float4 v = *(const float4*)&Mi[r * AS + c4];
                acc.x += fi[i] * v.x; acc.y += fi[i] * v.y;
                acc.z += fi[i] * v.z; acc.w += fi[i] * v.w;
            }
            float inv = 1.f / L;
            acc.x *= inv; acc.y *= inv; acc.z *= inv; acc.w *= inv;
            *(float4*)&ob[(size_t)r * Hn + c4] = acc;
        }
    }
}

// ================= launcher =================
extern "C" void kernel_launch(void* const* d_in, const int* in_sizes, int n_in,
                              void* d_out, int out_size)
{
    const float* x  = (const float*)d_in[0];
    const float* Wq = (const float*)d_in[1];
    const float* Wk = (const float*)d_in[2];
    const float* Wv = (const float*)d_in[3];
    float* out = (float*)d_out;

    int qkv_smem = 2 * (64 * XS_ST + PKC * WS_ST) * (int)sizeof(float);   // 68608
    cudaFuncSetAttribute(qkv_kernel, cudaFuncAttributeMaxDynamicSharedMemorySize, qkv_smem);
    qkv_kernel<<<(Bn * Tn) / 64, 128, qkv_smem>>>(x, Wq, Wk, Wv);

    int attn_smem = 13 * 64 * AS * (int)sizeof(uu);                       // 226304
    cudaFuncSetAttribute(attn_kernel, cudaFuncAttributeMaxDynamicSharedMemorySize, attn_smem);
    attn_kernel<<<Bn * 32, 384, attn_smem>>>(out);
}

// round 7
// speedup vs baseline: 1.1224x; 1.1224x over previous
#include <cuda_runtime.h>

#define Bn 4
#define Tn 4096
#define En 1024
#define Hn 64
#define SCALE 0.03125f   // 1024^-0.5

typedef unsigned uu;

// Projected tensors, pre-converted to tf32 bit patterns by qkv_kernel:
//  g_q[b][tok][h']  (SCALE folded, h sigma-permuted)
//  g_k[b][tok][h']  (h sigma-permuted)
//  g_vt[b][h][tok]  (transposed, natural order)
__device__ uu g_q[Bn * Tn * Hn];
__device__ uu g_k[Bn * Tn * Hn];
__device__ uu g_vt[Bn * Hn * Tn];

__device__ __forceinline__ uu f2tf(float f) {
    uu r; asm("cvt.rna.tf32.f32 %0, %1;" : "=r"(r) : "f"(f)); return r;
}

// D += A(16x8,row) * B(8x8,col), tf32 in, fp32 accum
__device__ __forceinline__ void mma8(float c[4], const uu a[4], const uu b[2]) {
    asm("mma.sync.aligned.m16n8k8.row.col.f32.tf32.tf32.f32 "
        "{%0,%1,%2,%3}, {%4,%5,%6,%7}, {%8,%9}, {%0,%1,%2,%3};"
        : "+f"(c[0]), "+f"(c[1]), "+f"(c[2]), "+f"(c[3])
        : "r"(a[0]), "r"(a[1]), "r"(a[2]), "r"(a[3]), "r"(b[0]), "r"(b[1]));
}

// group-scoped named barrier (128 threads)
__device__ __forceinline__ void barg(int id) {
    asm volatile("bar.sync %0, %1;" :: "r"(id), "r"(128) : "memory");
}

__device__ __forceinline__ void cpa16(void* s, const void* g) {
    unsigned sa = (unsigned)__cvta_generic_to_shared(s);
    asm volatile("cp.async.ca.shared.global [%0], [%1], 16;" :: "r"(sa), "l"(g));
}
__device__ __forceinline__ void cpa_commit() {
    asm volatile("cp.async.commit_group;" ::: "memory");
}
__device__ __forceinline__ void cpa_wait1() {
    asm volatile("cp.async.wait_group 1;" ::: "memory");
}
__device__ __forceinline__ void cpa_wait0() {
    asm volatile("cp.async.wait_group 0;" ::: "memory");
}

// ================= QKV projection =================
// Mainloop as R5; epilogue writes tf32 bits: q (scaled, sigma-permuted h),
// k (sigma-permuted h), v transposed into g_vt[h][token].
#define PKC 32
#define XS_ST 36
#define WS_ST 196

__global__ void __launch_bounds__(128, 2) qkv_kernel(
    const float* __restrict__ x,  const float* __restrict__ Wq,
    const float* __restrict__ Wk, const float* __restrict__ Wv)
{
    extern __shared__ float smf[];
    float* xsb = smf;
    float* wsb = smf + 2 * 64 * XS_ST;

    const int tid = threadIdx.x;
    const int w = tid >> 5, lane = tid & 31, gr = lane >> 2, t = lane & 3;
    const int row0 = blockIdx.x * 64;
    const float* Ws[3] = { Wq, Wk, Wv };

    float acc[4][6][4];
#pragma unroll
    for (int rb = 0; rb < 4; rb++)
#pragma unroll
        for (int nt = 0; nt < 6; nt++)
#pragma unroll
            for (int c = 0; c < 4; c++) acc[rb][nt][c] = 0.f;

    auto issue = [&](int k0, int s) {
        float* xs = xsb + s * 64 * XS_ST;
        float* ws = wsb + s * PKC * WS_ST;
#pragma unroll
        for (int it = 0; it < 4; it++) {
            int idx = tid + it * 128;
            int r = idx >> 3, c = (idx & 7) * 4;
            cpa16(&xs[r * XS_ST + c], &x[(size_t)(row0 + r) * En + k0 + c]);
        }
#pragma unroll
        for (int it = 0; it < 12; it++) {
            int idx = tid + it * 128;
            int kk = idx / 48, n4 = (idx % 48) * 4;
            int m = n4 >> 6, col = n4 & 63;
            cpa16(&ws[kk * WS_ST + n4], &Ws[m][(size_t)(k0 + kk) * Hn + col]);
        }
    };

    issue(0, 0);
    cpa_commit();

    for (int it = 0; it < En / PKC; it++) {
        __syncthreads();
        if (it + 1 < En / PKC) issue((it + 1) * PKC, (it + 1) & 1);
        cpa_commit();
        cpa_wait1();
        __syncthreads();

        const float* xs = xsb + (it & 1) * 64 * XS_ST;
        const float* ws = wsb + (it & 1) * PKC * WS_ST;
#pragma unroll
        for (int kk = 0; kk < PKC / 8; kk++) {
            uu a[4][4];
#pragma unroll
            for (int rb = 0; rb < 4; rb++) {
                int r = rb * 16 + gr;
                a[rb][0] = f2tf(xs[r * XS_ST + kk * 8 + t]);
                a[rb][1] = f2tf(xs[(r + 8) * XS_ST + kk * 8 + t]);
                a[rb][2] = f2tf(xs[r * XS_ST + kk * 8 + t + 4]);
                a[rb][3] = f2tf(xs[(r + 8) * XS_ST + kk * 8 + t + 4]);
            }
#pragma unroll
            for (int nt = 0; nt < 6; nt++) {
                int n0 = w * 48 + nt * 8;
                uu b[2];
                b[0] = f2tf(ws[(kk * 8 + t) * WS_ST + n0 + gr]);
                b[1] = f2tf(ws[(kk * 8 + t + 4) * WS_ST + n0 + gr]);
#pragma unroll
                for (int rb = 0; rb < 4; rb++) mma8(acc[rb][nt], a[rb], b);
            }
        }
    }

    // ---- epilogue ----
    const int bb = row0 >> 12;          // batch (blocks never straddle)
    const int tok0 = row0 & 4095;
    // sigma position for within-8-block offset 2t: p(off) = off<4 ? 2*off : 2*(off-4)+1
    const int p0 = (t < 2) ? 4 * t : 4 * t - 7;   // pos of offset 2t ; 2t+1 -> p0+2
#pragma unroll
    for (int nt = 0; nt < 6; nt++) {
        int n = w * 48 + nt * 8 + 2 * t;
        if (n < 128) {
            uu* base = (n < 64) ? g_q : g_k;
            float sc = (n < 64) ? SCALE : 1.f;
            int hb = (n & 63) & ~7;
#pragma unroll
            for (int rb = 0; rb < 4; rb++) {
                size_t r = (size_t)(row0 + rb * 16 + gr);
                base[r * Hn + hb + p0]           = f2tf(acc[rb][nt][0] * sc);
                base[r * Hn + hb + p0 + 2]       = f2tf(acc[rb][nt][1] * sc);
                base[(r + 8) * Hn + hb + p0]     = f2tf(acc[rb][nt][2] * sc);
                base[(r + 8) * Hn + hb + p0 + 2] = f2tf(acc[rb][nt][3] * sc);
            }
        } else {
            int h0 = n - 128;
            uu* vr0 = g_vt + ((size_t)bb * Hn + h0) * Tn;
            uu* vr1 = vr0 + Tn;
#pragma unroll
            for (int rb = 0; rb < 4; rb++) {
                int tk = tok0 + rb * 16 + gr;
                vr0[tk]     = f2tf(acc[rb][nt][0]);
                vr1[tk]     = f2tf(acc[rb][nt][1]);
                vr0[tk + 8] = f2tf(acc[rb][nt][2]);
                vr1[tk + 8] = f2tf(acc[rb][nt][3]);
            }
        }
    }
}

// ================= Flash attention: 3 kt-groups x (2x2) 32x32 warp tiles =================
// Pre-converted tf32 gmem -> cp.async bit-copy loads, LDS.64 fragments,
// shuffle-free P (S c-frag == P a-frag after key-permutation absorbed into V reads).
#define AS2 72   // stride: banks = 8*(row%4)+2t -> LDS.64 conflict-free
#define NG 3

__global__ void __launch_bounds__(384, 1) attn_kernel(float* __restrict__ out)
{
    extern __shared__ uu sm[];
    const int tid = threadIdx.x;
    const int w = tid >> 5, lane = tid & 31, gr = lane >> 2, t = lane & 3;
    const int g = w >> 2, wq = w & 3;
    const int rw = wq >> 1, cw = wq & 1;
    const int tg = tid & 127;

    uu* qs  = sm;                                   // strip 0: Q tile
    uu* ksg = sm + (size_t)(1 + g) * 64 * AS2;      // strips 1..3: K per group
    uu* vts = sm + (size_t)(4 + g) * 64 * AS2;      // strips 4..6: V^T per group
    float* Mg = (float*)(sm + (size_t)(1 + 2 * g + cw) * 64 * AS2);  // merge alias

    const int b = blockIdx.x & 3, pr = blockIdx.x >> 2;
    const uu* kg  = g_k  + (size_t)b * Tn * Hn;
    const uu* vtb = g_vt + (size_t)b * Hn * Tn;

    const int rbase = rw * 32, cbase = cw * 32;

    for (int hf = 0; hf < 2; hf++) {
        const int qt = hf ? pr : 63 - pr;
        __syncthreads();   // previous half's combine readers done

        // Q tile: pure bit-copy (16 KB contiguous)
        const uu* qg = g_q + ((size_t)b * Tn + qt * 64) * Hn;
        for (int idx = tid; idx < 1024; idx += 384)
            cpa16(&qs[(idx >> 4) * AS2 + (idx & 15) * 4], qg + idx * 4);
        cpa_commit();
        cpa_wait0();
        __syncthreads();

        float o[2][8][4];
        float mm[2][2], ll[2][2];
#pragma unroll
        for (int rb = 0; rb < 2; rb++) {
            mm[rb][0] = mm[rb][1] = -1e30f;
            ll[rb][0] = ll[rb][1] = 0.f;
#pragma unroll
            for (int ht = 0; ht < 8; ht++)
#pragma unroll
                for (int c = 0; c < 4; c++) o[rb][ht][c] = 0.f;
        }

        for (int kt = g; kt <= qt; kt += NG) {
            barg(g + 1);   // group's readers done with ksg/vts
            const uu* kp = kg + (size_t)kt * 64 * Hn;   // 16 KB contiguous
#pragma unroll
            for (int it = 0; it < 8; it++) {
                int idx = tg + it * 128;
                int r = idx >> 4, c4 = (idx & 15) * 4;
                cpa16(&ksg[r * AS2 + c4], kp + idx * 4);
                cpa16(&vts[r * AS2 + c4], vtb + (size_t)r * Tn + kt * 64 + c4);
            }
            cpa_commit();
            cpa_wait0();
            barg(g + 1);   // tile visible to whole group

            // ---- stage 1: S(32x32) = Q K^T (LDS.64 frags) ----
            float s[2][4][4];
#pragma unroll
            for (int rb = 0; rb < 2; rb++)
#pragma unroll
                for (int nt = 0; nt < 4; nt++)
#pragma unroll
                    for (int c = 0; c < 4; c++) s[rb][nt][c] = 0.f;
#pragma unroll
            for (int kk = 0; kk < 8; kk++) {
                uu qa[2][4];
#pragma unroll
                for (int rb = 0; rb < 2; rb++) {
                    int ra = (rbase + rb * 16 + gr) * AS2 + kk * 8 + 2 * t;
                    uint2 u0 = *(const uint2*)&qs[ra];            // (a0, a2)
                    uint2 u1 = *(const uint2*)&qs[ra + 8 * AS2];  // (a1, a3)
                    qa[rb][0] = u0.x; qa[rb][1] = u1.x;
                    qa[rb][2] = u0.y; qa[rb][3] = u1.y;
                }
#pragma unroll
                for (int nt = 0; nt < 4; nt++) {
                    uint2 kb = *(const uint2*)&ksg[(cbase + nt * 8 + gr) * AS2 + kk * 8 + 2 * t];
                    uu bf[2] = { kb.x, kb.y };
                    mma8(s[0][nt], qa[0], bf);
                    mma8(s[1][nt], qa[1], bf);
                }
            }

            if (kt == qt) {   // causal mask on diagonal tile (local 64x64 coords)
#pragma unroll
                for (int rb = 0; rb < 2; rb++) {
                    int r0 = rbase + rb * 16 + gr, r1 = r0 + 8;
#pragma unroll
                    for (int nt = 0; nt < 4; nt++) {
                        int c0 = cbase + nt * 8 + 2 * t;
                        if (c0 > r0)     s[rb][nt][0] = -1e30f;
                        if (c0 + 1 > r0) s[rb][nt][1] = -1e30f;
                        if (c0 > r1)     s[rb][nt][2] = -1e30f;
                        if (c0 + 1 > r1) s[rb][nt][3] = -1e30f;
                    }
                }
            }

            // ---- online softmax (skip O-rescale when max unchanged: exact) ----
#pragma unroll
            for (int rb = 0; rb < 2; rb++) {
                float rm0 = -1e30f, rm1 = -1e30f;
#pragma unroll
                for (int nt = 0; nt < 4; nt++) {
                    rm0 = fmaxf(rm0, fmaxf(s[rb][nt][0], s[rb][nt][1]));
                    rm1 = fmaxf(rm1, fmaxf(s[rb][nt][2], s[rb][nt][3]));
                }
                rm0 = fmaxf(rm0, __shfl_xor_sync(~0u, rm0, 1));
                rm0 = fmaxf(rm0, __shfl_xor_sync(~0u, rm0, 2));
                rm1 = fmaxf(rm1, __shfl_xor_sync(~0u, rm1, 1));
                rm1 = fmaxf(rm1, __shfl_xor_sync(~0u, rm1, 2));
                float nm0 = fmaxf(mm[rb][0], rm0), nm1 = fmaxf(mm[rb][1], rm1);
                bool chg = (nm0 != mm[rb][0]) || (nm1 != mm[rb][1]);
                unsigned any = __ballot_sync(~0u, chg);

                float rs0 = 0.f, rs1 = 0.f;
#pragma unroll
                for (int nt = 0; nt < 4; nt++) {
                    float p0 = __expf(s[rb][nt][0] - nm0), p1 = __expf(s[rb][nt][1] - nm0);
                    float p2 = __expf(s[rb][nt][2] - nm1), p3 = __expf(s[rb][nt][3] - nm1);
                    rs0 += p0 + p1; rs1 += p2 + p3;
                    s[rb][nt][0] = __uint_as_float(f2tf(p0));
                    s[rb][nt][1] = __uint_as_float(f2tf(p1));
                    s[rb][nt][2] = __uint_as_float(f2tf(p2));
                    s[rb][nt][3] = __uint_as_float(f2tf(p3));
                }
                rs0 += __shfl_xor_sync(~0u, rs0, 1);
                rs0 += __shfl_xor_sync(~0u, rs0, 2);
                rs1 += __shfl_xor_sync(~0u, rs1, 1);
                rs1 += __shfl_xor_sync(~0u, rs1, 2);

                if (any) {
                    float cr0 = __expf(mm[rb][0] - nm0);
                    float cr1 = __expf(mm[rb][1] - nm1);
                    ll[rb][0] = ll[rb][0] * cr0 + rs0;
                    ll[rb][1] = ll[rb][1] * cr1 + rs1;
#pragma unroll
                    for (int ht = 0; ht < 8; ht++) {
                        o[rb][ht][0] *= cr0; o[rb][ht][1] *= cr0;
                        o[rb][ht][2] *= cr1; o[rb][ht][3] *= cr1;
                    }
                } else {
                    ll[rb][0] += rs0;
                    ll[rb][1] += rs1;
                }
                mm[rb][0] = nm0; mm[rb][1] = nm1;
            }

            // ---- stage 2: O += P V  (P a-frag = S c-frag reordered; V^T LDS.64) ----
#pragma unroll
            for (int kk = 0; kk < 4; kk++) {
                uu pa[2][4];
#pragma unroll
                for (int rb = 0; rb < 2; rb++) {
                    pa[rb][0] = __float_as_uint(s[rb][kk][0]);
                    pa[rb][1] = __float_as_uint(s[rb][kk][2]);
                    pa[rb][2] = __float_as_uint(s[rb][kk][1]);
                    pa[rb][3] = __float_as_uint(s[rb][kk][3]);
                }
#pragma unroll
                for (int ht = 0; ht < 8; ht++) {
                    uint2 vv = *(const uint2*)&vts[(ht * 8 + gr) * AS2 + cbase + kk * 8 + 2 * t];
                    uu vb[2] = { vv.x, vv.y };
                    mma8(o[0][ht], pa[0], vb);
                    mma8(o[1][ht], pa[1], vb);
                }
            }
        }

        // ---- dump 6 partials into strips 1..6 (staging dead now) ----
        __syncthreads();
#pragma unroll
        for (int rb = 0; rb < 2; rb++) {
            int r0 = rbase + rb * 16 + gr, r1 = r0 + 8;
#pragma unroll
            for (int ht = 0; ht < 8; ht++) {
                *(float2*)&Mg[r0 * AS2 + ht * 8 + 2 * t] = make_float2(o[rb][ht][0], o[rb][ht][1]);
                *(float2*)&Mg[r1 * AS2 + ht * 8 + 2 * t] = make_float2(o[rb][ht][2], o[rb][ht][3]);
            }
            if (t == 0) {
                Mg[r0 * AS2 + 64] = mm[rb][0]; Mg[r0 * AS2 + 65] = ll[rb][0];
                Mg[r1 * AS2 + 64] = mm[rb][1]; Mg[r1 * AS2 + 65] = ll[rb][1];
            }
        }
        __syncthreads();

        // ---- combine 6 partials, write output ----
        float* ob = out + ((size_t)b * Tn + qt * 64) * Hn;
        for (int idx = tid; idx < 1024; idx += 384) {
            int r = idx >> 4, c4 = (idx & 15) * 4;
            float mi[6], li[6], Mx = -1e30f;
#pragma unroll
            for (int i = 0; i < 6; i++) {
                const float* Mi = (const float*)(sm + (size_t)(1 + i) * 64 * AS2);
                mi[i] = Mi[r * AS2 + 64];
                li[i] = Mi[r * AS2 + 65];
                Mx = fmaxf(Mx, mi[i]);
            }
            float L = 0.f, fi[6];
#pragma unroll
            for (int i = 0; i < 6; i++) {
                fi[i] = __expf(mi[i] - Mx);
                L += li[i] * fi[i];
            }
            float4 acc = make_float4(0.f, 0.f, 0.f, 0.f);
#pragma unroll
            for (int i = 0; i < 6; i++) {
                const float* Mi = (const float*)(sm + (size_t)(1 + i) * 64 * AS2);
                float4 v = *(const float4*)&Mi[r * AS2 + c4];
                acc.x += fi[i] * v.x; acc.y += fi[i] * v.y;
                acc.z += fi[i] * v.z; acc.w += fi[i] * v.w;
            }
            float inv = 1.f / L;
            acc.x *= inv; acc.y *= inv; acc.z *= inv; acc.w *= inv;
            *(float4*)&ob[(size_t)r * Hn + c4] = acc;
        }
    }
}

// ================= launcher =================
extern "C" void kernel_launch(void* const* d_in, const int* in_sizes, int n_in,
                              void* d_out, int out_size)
{
    const float* x  = (const float*)d_in[0];
    const float* Wq = (const float*)d_in[1];
    const float* Wk = (const float*)d_in[2];
    const float* Wv = (const float*)d_in[3];
    float* out = (float*)d_out;

    int qkv_smem = 2 * (64 * XS_ST + PKC * WS_ST) * (int)sizeof(float);   // 68608
    cudaFuncSetAttribute(qkv_kernel, cudaFuncAttributeMaxDynamicSharedMemorySize, qkv_smem);
    qkv_kernel<<<(Bn * Tn) / 64, 128, qkv_smem>>>(x, Wq, Wk, Wv);

    int attn_smem = 7 * 64 * AS2 * (int)sizeof(uu);                       // 129024
    cudaFuncSetAttribute(attn_kernel, cudaFuncAttributeMaxDynamicSharedMemorySize, attn_smem);
    attn_kernel<<<Bn * 32, 384, attn_smem>>>(out);
}

// round 8
// speedup vs baseline: 1.1578x; 1.0316x over previous
#include <cuda_runtime.h>

#define Bn 4
#define Tn 4096
#define En 1024
#define Hn 64
#define SCALE 0.03125f   // 1024^-0.5
#define LOG2E 1.44269504088896340736f

typedef unsigned uu;

// Projected tensors (tf32 bit patterns, written by qkv_kernel):
//  g_q[b][tok][h']  (SCALE*log2e folded via Wq, h sigma-permuted)
//  g_k[b][tok][h']  (h sigma-permuted)
//  g_vt[b][h][tok]  (transposed, natural order)
__device__ uu g_q[Bn * Tn * Hn];
__device__ uu g_k[Bn * Tn * Hn];
__device__ uu g_vt[Bn * Hn * Tn];
// W pre-converted to tf32 bits: [m][k][n], m in {q(scaled), k, v}
__device__ uu g_wt[3 * En * Hn];

__device__ __forceinline__ uu f2tf(float f) {
    uu r; asm("cvt.rna.tf32.f32 %0, %1;" : "=r"(r) : "f"(f)); return r;
}

// D += A(16x8,row) * B(8x8,col), tf32 in, fp32 accum
__device__ __forceinline__ void mma8(float c[4], const uu a[4], const uu b[2]) {
    asm("mma.sync.aligned.m16n8k8.row.col.f32.tf32.tf32.f32 "
        "{%0,%1,%2,%3}, {%4,%5,%6,%7}, {%8,%9}, {%0,%1,%2,%3};"
        : "+f"(c[0]), "+f"(c[1]), "+f"(c[2]), "+f"(c[3])
        : "r"(a[0]), "r"(a[1]), "r"(a[2]), "r"(a[3]), "r"(b[0]), "r"(b[1]));
}

// group-scoped named barrier (128 threads)
__device__ __forceinline__ void barg(int id) {
    asm volatile("bar.sync %0, %1;" :: "r"(id), "r"(128) : "memory");
}

__device__ __forceinline__ void cpa16(void* s, const void* g) {
    unsigned sa = (unsigned)__cvta_generic_to_shared(s);
    asm volatile("cp.async.ca.shared.global [%0], [%1], 16;" :: "r"(sa), "l"(g));
}
__device__ __forceinline__ void cpa_commit() {
    asm volatile("cp.async.commit_group;" ::: "memory");
}
__device__ __forceinline__ void cpa_wait1() {
    asm volatile("cp.async.wait_group 1;" ::: "memory");
}
__device__ __forceinline__ void cpa_wait0() {
    asm volatile("cp.async.wait_group 0;" ::: "memory");
}

// ================= W pre-convert: fp32 -> tf32 bits, q-scale folded =================
__global__ void wconv_kernel(const float* __restrict__ Wq,
                             const float* __restrict__ Wk,
                             const float* __restrict__ Wv)
{
    int idx = blockIdx.x * 256 + threadIdx.x;      // 0..196607
    int m = idx >> 16, j = idx & 65535;
    const float* W = (m == 0) ? Wq : (m == 1 ? Wk : Wv);
    float sc = (m == 0) ? (SCALE * LOG2E) : 1.f;
    g_wt[idx] = f2tf(W[j] * sc);
}

// ================= QKV projection =================
// cp.async pipeline; x staged fp32 (cvt at a-frag), W staged as tf32 bits (raw b-frag).
// Epilogue: q/k sigma-permuted tf32 to g_q/g_k; v transposed to g_vt.
#define PKC 32
#define XS_ST 36
#define WS_ST 196

__global__ void __launch_bounds__(128, 2) qkv_kernel(const float* __restrict__ x)
{
    extern __shared__ float smf[];
    float* xsb = smf;
    uu* wsb = (uu*)(smf + 2 * 64 * XS_ST);

    const int tid = threadIdx.x;
    const int w = tid >> 5, lane = tid & 31, gr = lane >> 2, t = lane & 3;
    const int row0 = blockIdx.x * 64;

    float acc[4][6][4];
#pragma unroll
    for (int rb = 0; rb < 4; rb++)
#pragma unroll
        for (int nt = 0; nt < 6; nt++)
#pragma unroll
            for (int c = 0; c < 4; c++) acc[rb][nt][c] = 0.f;

    auto issue = [&](int k0, int s) {
        float* xs = xsb + s * 64 * XS_ST;
        uu* ws = wsb + s * PKC * WS_ST;
#pragma unroll
        for (int it = 0; it < 4; it++) {
            int idx = tid + it * 128;
            int r = idx >> 3, c = (idx & 7) * 4;
            cpa16(&xs[r * XS_ST + c], &x[(size_t)(row0 + r) * En + k0 + c]);
        }
#pragma unroll
        for (int it = 0; it < 12; it++) {
            int idx = tid + it * 128;
            int kk = idx / 48, n4 = (idx % 48) * 4;
            int m = n4 >> 6, col = n4 & 63;
            cpa16(&ws[kk * WS_ST + n4], &g_wt[(size_t)m * En * Hn + (size_t)(k0 + kk) * Hn + col]);
        }
    };

    issue(0, 0);
    cpa_commit();

    for (int it = 0; it < En / PKC; it++) {
        __syncthreads();
        if (it + 1 < En / PKC) issue((it + 1) * PKC, (it + 1) & 1);
        cpa_commit();
        cpa_wait1();
        __syncthreads();

        const float* xs = xsb + (it & 1) * 64 * XS_ST;
        const uu* ws = wsb + (it & 1) * PKC * WS_ST;
#pragma unroll
        for (int kk = 0; kk < PKC / 8; kk++) {
            uu a[4][4];
#pragma unroll
            for (int rb = 0; rb < 4; rb++) {
                int r = rb * 16 + gr;
                a[rb][0] = f2tf(xs[r * XS_ST + kk * 8 + t]);
                a[rb][1] = f2tf(xs[(r + 8) * XS_ST + kk * 8 + t]);
                a[rb][2] = f2tf(xs[r * XS_ST + kk * 8 + t + 4]);
                a[rb][3] = f2tf(xs[(r + 8) * XS_ST + kk * 8 + t + 4]);
            }
#pragma unroll
            for (int nt = 0; nt < 6; nt++) {
                int n0 = w * 48 + nt * 8;
                uu b[2];
                b[0] = ws[(kk * 8 + t) * WS_ST + n0 + gr];
                b[1] = ws[(kk * 8 + t + 4) * WS_ST + n0 + gr];
#pragma unroll
                for (int rb = 0; rb < 4; rb++) mma8(acc[rb][nt], a[rb], b);
            }
        }
    }

    // ---- epilogue ----
    const int bb = row0 >> 12;
    const int tok0 = row0 & 4095;
    // sigma position for within-8-block offset 2t: pos(off) = off<4 ? 2*off : 2*(off-4)+1
    const int p0 = (t < 2) ? 4 * t : 4 * t - 7;
#pragma unroll
    for (int nt = 0; nt < 6; nt++) {
        int n = w * 48 + nt * 8 + 2 * t;
        if (n < 128) {
            uu* base = (n < 64) ? g_q : g_k;
            int hb = (n & 63) & ~7;
#pragma unroll
            for (int rb = 0; rb < 4; rb++) {
                size_t r = (size_t)(row0 + rb * 16 + gr);
                base[r * Hn + hb + p0]           = f2tf(acc[rb][nt][0]);
                base[r * Hn + hb + p0 + 2]       = f2tf(acc[rb][nt][1]);
                base[(r + 8) * Hn + hb + p0]     = f2tf(acc[rb][nt][2]);
                base[(r + 8) * Hn + hb + p0 + 2] = f2tf(acc[rb][nt][3]);
            }
        } else {
            int h0 = n - 128;
            uu* vr0 = g_vt + ((size_t)bb * Hn + h0) * Tn;
            uu* vr1 = vr0 + Tn;
#pragma unroll
            for (int rb = 0; rb < 4; rb++) {
                int tk = tok0 + rb * 16 + gr;
                vr0[tk]     = f2tf(acc[rb][nt][0]);
                vr1[tk]     = f2tf(acc[rb][nt][1]);
                vr0[tk + 8] = f2tf(acc[rb][nt][2]);
                vr1[tk + 8] = f2tf(acc[rb][nt][3]);
            }
        }
    }
}

// ================= Flash attention: 256 blocks (one q-tile each, heavy first) =================
// 3 kt-groups x (2x2) 32x32 warp tiles; exp2-domain softmax (log2e folded in q).
#define AS2 72
#define NG 3

__global__ void __launch_bounds__(384, 1) attn_kernel(float* __restrict__ out)
{
    extern __shared__ uu sm[];
    const int tid = threadIdx.x;
    const int w = tid >> 5, lane = tid & 31, gr = lane >> 2, t = lane & 3;
    const int g = w >> 2, wq = w & 3;
    const int rw = wq >> 1, cw = wq & 1;
    const int tg = tid & 127;

    uu* qs  = sm;                                   // strip 0: Q tile
    uu* ksg = sm + (size_t)(1 + g) * 64 * AS2;      // strips 1..3: K per group
    uu* vts = sm + (size_t)(4 + g) * 64 * AS2;      // strips 4..6: V^T per group
    float* Mg = (float*)(sm + (size_t)(1 + 2 * g + cw) * 64 * AS2);  // merge alias

    const int b = blockIdx.x & 3;
    const int qt = 63 - (blockIdx.x >> 2);          // heavy q-tiles launch first
    const uu* kg  = g_k  + (size_t)b * Tn * Hn;
    const uu* vtb = g_vt + (size_t)b * Hn * Tn;

    const int rbase = rw * 32, cbase = cw * 32;

    // Q tile: pure bit-copy (16 KB contiguous)
    const uu* qg = g_q + ((size_t)b * Tn + qt * 64) * Hn;
    for (int idx = tid; idx < 1024; idx += 384)
        cpa16(&qs[(idx >> 4) * AS2 + (idx & 15) * 4], qg + idx * 4);
    cpa_commit();
    cpa_wait0();
    __syncthreads();

    float o[2][8][4];
    float mm[2][2], ll[2][2];
#pragma unroll
    for (int rb = 0; rb < 2; rb++) {
        mm[rb][0] = mm[rb][1] = -1e30f;
        ll[rb][0] = ll[rb][1] = 0.f;
#pragma unroll
        for (int ht = 0; ht < 8; ht++)
#pragma unroll
            for (int c = 0; c < 4; c++) o[rb][ht][c] = 0.f;
    }

    for (int kt = g; kt <= qt; kt += NG) {
        barg(g + 1);   // group's readers done with ksg/vts
        const uu* kp = kg + (size_t)kt * 64 * Hn;
#pragma unroll
        for (int it = 0; it < 8; it++) {
            int idx = tg + it * 128;
            int r = idx >> 4, c4 = (idx & 15) * 4;
            cpa16(&ksg[r * AS2 + c4], kp + idx * 4);
            cpa16(&vts[r * AS2 + c4], vtb + (size_t)r * Tn + kt * 64 + c4);
        }
        cpa_commit();
        cpa_wait0();
        barg(g + 1);   // tile visible to whole group

        // ---- stage 1: S(32x32) = Q K^T (LDS.64 frags; scores in log2 domain) ----
        float s[2][4][4];
#pragma unroll
        for (int rb = 0; rb < 2; rb++)
#pragma unroll
            for (int nt = 0; nt < 4; nt++)
#pragma unroll
                for (int c = 0; c < 4; c++) s[rb][nt][c] = 0.f;
#pragma unroll
        for (int kk = 0; kk < 8; kk++) {
            uu qa[2][4];
#pragma unroll
            for (int rb = 0; rb < 2; rb++) {
                int ra = (rbase + rb * 16 + gr) * AS2 + kk * 8 + 2 * t;
                uint2 u0 = *(const uint2*)&qs[ra];
                uint2 u1 = *(const uint2*)&qs[ra + 8 * AS2];
                qa[rb][0] = u0.x; qa[rb][1] = u1.x;
                qa[rb][2] = u0.y; qa[rb][3] = u1.y;
            }
#pragma unroll
            for (int nt = 0; nt < 4; nt++) {
                uint2 kb = *(const uint2*)&ksg[(cbase + nt * 8 + gr) * AS2 + kk * 8 + 2 * t];
                uu bf[2] = { kb.x, kb.y };
                mma8(s[0][nt], qa[0], bf);
                mma8(s[1][nt], qa[1], bf);
            }
        }

        if (kt == qt) {   // causal mask on diagonal tile
#pragma unroll
            for (int rb = 0; rb < 2; rb++) {
                int r0 = rbase + rb * 16 + gr, r1 = r0 + 8;
#pragma unroll
                for (int nt = 0; nt < 4; nt++) {
                    int c0 = cbase + nt * 8 + 2 * t;
                    if (c0 > r0)     s[rb][nt][0] = -1e30f;
                    if (c0 + 1 > r0) s[rb][nt][1] = -1e30f;
                    if (c0 > r1)     s[rb][nt][2] = -1e30f;
                    if (c0 + 1 > r1) s[rb][nt][3] = -1e30f;
                }
            }
        }

        // ---- online softmax (base-2; skip O-rescale when max unchanged) ----
#pragma unroll
        for (int rb = 0; rb < 2; rb++) {
            float rm0 = -1e30f, rm1 = -1e30f;
#pragma unroll
            for (int nt = 0; nt < 4; nt++) {
                rm0 = fmaxf(rm0, fmaxf(s[rb][nt][0], s[rb][nt][1]));
                rm1 = fmaxf(rm1, fmaxf(s[rb][nt][2], s[rb][nt][3]));
            }
            rm0 = fmaxf(rm0, __shfl_xor_sync(~0u, rm0, 1));
            rm0 = fmaxf(rm0, __shfl_xor_sync(~0u, rm0, 2));
            rm1 = fmaxf(rm1, __shfl_xor_sync(~0u, rm1, 1));
            rm1 = fmaxf(rm1, __shfl_xor_sync(~0u, rm1, 2));
            float nm0 = fmaxf(mm[rb][0], rm0), nm1 = fmaxf(mm[rb][1], rm1);
            bool chg = (nm0 != mm[rb][0]) || (nm1 != mm[rb][1]);
            unsigned any = __ballot_sync(~0u, chg);

            float rs0 = 0.f, rs1 = 0.f;
#pragma unroll
            for (int nt = 0; nt < 4; nt++) {
                float p0 = exp2f(s[rb][nt][0] - nm0), p1 = exp2f(s[rb][nt][1] - nm0);
                float p2 = exp2f(s[rb][nt][2] - nm1), p3 = exp2f(s[rb][nt][3] - nm1);
                rs0 += p0 + p1; rs1 += p2 + p3;
                s[rb][nt][0] = __uint_as_float(f2tf(p0));
                s[rb][nt][1] = __uint_as_float(f2tf(p1));
                s[rb][nt][2] = __uint_as_float(f2tf(p2));
                s[rb][nt][3] = __uint_as_float(f2tf(p3));
            }
            rs0 += __shfl_xor_sync(~0u, rs0, 1);
            rs0 += __shfl_xor_sync(~0u, rs0, 2);
            rs1 += __shfl_xor_sync(~0u, rs1, 1);
            rs1 += __shfl_xor_sync(~0u, rs1, 2);

            if (any) {
                float cr0 = exp2f(mm[rb][0] - nm0);
                float cr1 = exp2f(mm[rb][1] - nm1);
                ll[rb][0] = ll[rb][0] * cr0 + rs0;
                ll[rb][1] = ll[rb][1] * cr1 + rs1;
#pragma unroll
                for (int ht = 0; ht < 8; ht++) {
                    o[rb][ht][0] *= cr0; o[rb][ht][1] *= cr0;
                    o[rb][ht][2] *= cr1; o[rb][ht][3] *= cr1;
                }
            } else {
                ll[rb][0] += rs0;
                ll[rb][1] += rs1;
            }
            mm[rb][0] = nm0; mm[rb][1] = nm1;
        }

        // ---- stage 2: O += P V (P a-frag = S c-frag reordered; V^T LDS.64) ----
#pragma unroll
        for (int kk = 0; kk < 4; kk++) {
            uu pa[2][4];
#pragma unroll
            for (int rb = 0; rb < 2; rb++) {
                pa[rb][0] = __float_as_uint(s[rb][kk][0]);
                pa[rb][1] = __float_as_uint(s[rb][kk][2]);
                pa[rb][2] = __float_as_uint(s[rb][kk][1]);
                pa[rb][3] = __float_as_uint(s[rb][kk][3]);
            }
#pragma unroll
            for (int ht = 0; ht < 8; ht++) {
                uint2 vv = *(const uint2*)&vts[(ht * 8 + gr) * AS2 + cbase + kk * 8 + 2 * t];
                uu vb[2] = { vv.x, vv.y };
                mma8(o[0][ht], pa[0], vb);
                mma8(o[1][ht], pa[1], vb);
            }
        }
    }

    // ---- dump 6 partials into strips 1..6 (staging dead now) ----
    __syncthreads();
#pragma unroll
    for (int rb = 0; rb < 2; rb++) {
        int r0 = rbase + rb * 16 + gr, r1 = r0 + 8;
#pragma unroll
        for (int ht = 0; ht < 8; ht++) {
            *(float2*)&Mg[r0 * AS2 + ht * 8 + 2 * t] = make_float2(o[rb][ht][0], o[rb][ht][1]);
            *(float2*)&Mg[r1 * AS2 + ht * 8 + 2 * t] = make_float2(o[rb][ht][2], o[rb][ht][3]);
        }
        if (t == 0) {
            Mg[r0 * AS2 + 64] = mm[rb][0]; Mg[r0 * AS2 + 65] = ll[rb][0];
            Mg[r1 * AS2 + 64] = mm[rb][1]; Mg[r1 * AS2 + 65] = ll[rb][1];
        }
    }
    __syncthreads();

    // ---- combine 6 partials, write output ----
    float* ob = out + ((size_t)b * Tn + qt * 64) * Hn;
    for (int idx = tid; idx < 1024; idx += 384) {
        int r = idx >> 4, c4 = (idx & 15) * 4;
        float mi[6], li[6], Mx = -1e30f;
#pragma unroll
        for (int i = 0; i < 6; i++) {
            const float* Mi = (const float*)(sm + (size_t)(1 + i) * 64 * AS2);
            mi[i] = Mi[r * AS2 + 64];
            li[i] = Mi[r * AS2 + 65];
            Mx = fmaxf(Mx, mi[i]);
        }
        float L = 0.f, fi[6];
#pragma unroll
        for (int i = 0; i < 6; i++) {
            fi[i] = exp2f(mi[i] - Mx);
            L += li[i] * fi[i];
        }
        float4 acc = make_float4(0.f, 0.f, 0.f, 0.f);
#pragma unroll
        for (int i = 0; i < 6; i++) {
            const float* Mi = (const float*)(sm + (size_t)(1 + i) * 64 * AS2);
            float4 v = *(const float4*)&Mi[r * AS2 + c4];
            acc.x += fi[i] * v.x; acc.y += fi[i] * v.y;
            acc.z += fi[i] * v.z; acc.w += fi[i] * v.w;
        }
        float inv = 1.f / L;
        acc.x *= inv; acc.y *= inv; acc.z *= inv; acc.w *= inv;
        *(float4*)&ob[(size_t)r * Hn + c4] = acc;
    }
}

// ================= launcher =================
extern "C" void kernel_launch(void* const* d_in, const int* in_sizes, int n_in,
                              void* d_out, int out_size)
{
    const float* x  = (const float*)d_in[0];
    const float* Wq = (const float*)d_in[1];
    const float* Wk = (const float*)d_in[2];
    const float* Wv = (const float*)d_in[3];
    float* out = (float*)d_out;

    wconv_kernel<<<768, 256>>>(Wq, Wk, Wv);

    int qkv_smem = 2 * (64 * XS_ST + PKC * WS_ST) * (int)sizeof(float);   // 68608
    cudaFuncSetAttribute(qkv_kernel, cudaFuncAttributeMaxDynamicSharedMemorySize, qkv_smem);
    qkv_kernel<<<(Bn * Tn) / 64, 128, qkv_smem>>>(x);

    int attn_smem = 7 * 64 * AS2 * (int)sizeof(uu);                       // 129024
    cudaFuncSetAttribute(attn_kernel, cudaFuncAttributeMaxDynamicSharedMemorySize, attn_smem);
    attn_kernel<<<Bn * 64, 384, attn_smem>>>(out);
}